// round 5
// baseline (speedup 1.0000x reference)
#include <cuda_runtime.h>

#define NN 4096
#define IN_F 256
#define HD 512
#define NH 8
#define DD 64

// Scratch (no allocations allowed)
__device__ float g_h[NN * HD];      // h = inp @ W^T   [N, H*D]
__device__ float g_e1[NH * NN];     // exp(s[h][n])
__device__ float g_e2[NH * NN];     // exp(0.2*s[h][n])

// ---------------------------------------------------------------------------
// Kernel 1: h = inp @ W^T.  BM=128, BN=64, BK=16, 128 threads, 8x8 micro-tile.
// ---------------------------------------------------------------------------
__global__ __launch_bounds__(128) void gemm_h_kernel(
    const float* __restrict__ inp, const float* __restrict__ W)
{
    __shared__ float smA[16][128];   // [k][m]
    __shared__ float smB[16][64];    // [k][n]
    const int tid = threadIdx.x;
    const int m0 = blockIdx.y * 128;
    const int n0 = blockIdx.x * 64;
    const int tx = tid & 7;          // 0..7  -> 8 cols
    const int ty = tid >> 3;         // 0..15 -> 8 rows

    float acc[8][8];
#pragma unroll
    for (int r = 0; r < 8; r++)
#pragma unroll
        for (int c = 0; c < 8; c++) acc[r][c] = 0.f;

    for (int k0 = 0; k0 < IN_F; k0 += 16) {
        // inp tile 128x16 -> smA[k][m]
#pragma unroll
        for (int p = 0; p < 4; p++) {
            int r = p * 32 + (tid >> 2);
            int q = tid & 3;
            float4 v = *(const float4*)&inp[(size_t)(m0 + r) * IN_F + k0 + q * 4];
            smA[q * 4 + 0][r] = v.x; smA[q * 4 + 1][r] = v.y;
            smA[q * 4 + 2][r] = v.z; smA[q * 4 + 3][r] = v.w;
        }
        // W tile 64x16 -> smB[k][n]
#pragma unroll
        for (int p = 0; p < 2; p++) {
            int fid = p * 128 + tid;
            int nn = fid >> 2, q = fid & 3;
            float4 v = *(const float4*)&W[(size_t)(n0 + nn) * IN_F + k0 + q * 4];
            smB[q * 4 + 0][nn] = v.x; smB[q * 4 + 1][nn] = v.y;
            smB[q * 4 + 2][nn] = v.z; smB[q * 4 + 3][nn] = v.w;
        }
        __syncthreads();
#pragma unroll
        for (int k = 0; k < 16; k++) {
            float a[8], b[8];
#pragma unroll
            for (int r = 0; r < 8; r++) a[r] = smA[k][ty * 8 + r];
#pragma unroll
            for (int c = 0; c < 8; c++) b[c] = smB[k][tx * 8 + c];
#pragma unroll
            for (int r = 0; r < 8; r++)
#pragma unroll
                for (int c = 0; c < 8; c++) acc[r][c] += a[r] * b[c];
        }
        __syncthreads();
    }
#pragma unroll
    for (int r = 0; r < 8; r++)
#pragma unroll
        for (int c = 0; c < 8; c += 4) {
            float4 v = make_float4(acc[r][c], acc[r][c + 1], acc[r][c + 2], acc[r][c + 3]);
            *(float4*)&g_h[(size_t)(m0 + ty * 8 + r) * HD + n0 + tx * 8 + c] = v;
        }
}

// ---------------------------------------------------------------------------
// Kernel 2: s[h][n] = sum_d h[n,h,d]*a_left[h,d];  e1=exp(s), e2=exp(0.2 s).
// One warp per (n,h).
// ---------------------------------------------------------------------------
__global__ __launch_bounds__(256) void scores_kernel(const float* __restrict__ a_left)
{
    int gid  = blockIdx.x * 8 + (threadIdx.x >> 5);
    int lane = threadIdx.x & 31;
    int h = gid & 7;
    int n = gid >> 3;
    float2 v = *(const float2*)&g_h[(size_t)n * HD + h * DD + lane * 2];
    float2 a = *(const float2*)&a_left[h * DD + lane * 2];
    float p = v.x * a.x + v.y * a.y;
#pragma unroll
    for (int o = 16; o > 0; o >>= 1) p += __shfl_xor_sync(0xffffffffu, p, o);
    if (lane == 0) {
        g_e1[h * NN + n] = __expf(p);
        g_e2[h * NN + n] = __expf(0.2f * p);
    }
}

// ---------------------------------------------------------------------------
// Kernel 3: attention + PV.
// Grid (32 row-tiles, 8 heads), 128 threads, 2 CTAs/SM -> fully resident wave.
// Per j-tile (TJ=32):
//   phase 1: W[i][j] = max(e1i*e1j, e2i*e2j) * (A==0 ? 1 : exp(A))  -> smem
//   phase 2: acc[128x64] += W[128x32] * V[32x64]   (8x8 register tile)
// Denominators from a column sum of the weight tile; epilogue normalizes.
// ---------------------------------------------------------------------------
__global__ __launch_bounds__(128, 2) void attn_kernel(
    const float* __restrict__ Amat, float* __restrict__ out)
{
    __shared__ float Ws[128][33];    // [i][j], stride 33 -> conflict-free both ways
    __shared__ float Vt[32][64];     // [j][d]
    __shared__ float se1i[128], se2i[128], sden[128];

    const int tid  = threadIdx.x;
    const int h    = blockIdx.y;
    const int i0   = blockIdx.x * 128;
    const int lane = tid & 31;
    const int wid  = tid >> 5;
    const int tx   = tid & 7;        // 8 col-groups of 8 -> 64 d
    const int ty   = tid >> 3;       // 16 row-groups of 8 -> 128 rows

    se1i[tid] = g_e1[h * NN + i0 + tid];
    se2i[tid] = g_e2[h * NN + i0 + tid];
    sden[tid] = 0.f;

    float acc[8][8];
#pragma unroll
    for (int r = 0; r < 8; r++)
#pragma unroll
        for (int c = 0; c < 8; c++) acc[r][c] = 0.f;

    for (int j0 = 0; j0 < NN; j0 += 32) {
        __syncthreads();   // protects Ws/Vt reuse + first-iter se1i visibility

        // ---- load V tile: h[j0..j0+31, h*64 .. h*64+63] ----
#pragma unroll
        for (int p = 0; p < 4; p++) {
            int idx = p * 128 + tid;          // 0..511 float4s
            int j = idx >> 4, q = idx & 15;
            float4 v = *(const float4*)&g_h[(size_t)(j0 + j) * HD + h * DD + q * 4];
            *(float4*)&Vt[j][q * 4] = v;
        }

        // ---- phase 1: weight tile ----
        const float e1j = g_e1[h * NN + j0 + lane];
        const float e2j = g_e2[h * NN + j0 + lane];
#pragma unroll
        for (int p = 0; p < 32; p++) {
            int i = p * 4 + wid;
            float a = Amat[(size_t)(i0 + i) * NN + j0 + lane];
            float w = fmaxf(se1i[i] * e1j, se2i[i] * e2j);
            if (a != 0.0f) w *= __expf(a);    // warp-uniform skip when A==0
            Ws[i][lane] = w;
        }
        __syncthreads();

        // ---- softmax denominators: column sum of Ws (one row per thread) ----
        {
            float ds = 0.f;
#pragma unroll
            for (int k = 0; k < 32; k++) ds += Ws[tid][k];
            sden[tid] += ds;
        }

        // ---- phase 2: acc += Ws * Vt ----
#pragma unroll
        for (int k = 0; k < 32; k++) {
            float wv[8], vv[8];
#pragma unroll
            for (int r = 0; r < 8; r++) wv[r] = Ws[ty * 8 + r][k];
#pragma unroll
            for (int c = 0; c < 8; c++) vv[c] = Vt[k][tx * 8 + c];
#pragma unroll
            for (int r = 0; r < 8; r++)
#pragma unroll
                for (int c = 0; c < 8; c++) acc[r][c] += wv[r] * vv[c];
        }
    }
    __syncthreads();

    // ---- epilogue: normalize and store ----
#pragma unroll
    for (int r = 0; r < 8; r++) {
        float inv = 1.0f / sden[ty * 8 + r];
#pragma unroll
        for (int c = 0; c < 8; c += 4) {
            float4 v = make_float4(acc[r][c] * inv, acc[r][c + 1] * inv,
                                   acc[r][c + 2] * inv, acc[r][c + 3] * inv);
            *(float4*)&out[(size_t)(i0 + ty * 8 + r) * HD + h * DD + tx * 8 + c] = v;
        }
    }
}

// ---------------------------------------------------------------------------
extern "C" void kernel_launch(void* const* d_in, const int* in_sizes, int n_in,
                              void* d_out, int out_size)
{
    const float* inp    = (const float*)d_in[0];   // [4096, 256]
    const float* Amat   = (const float*)d_in[1];   // [4096, 4096]
    const float* W      = (const float*)d_in[2];   // [512, 256]
    const float* a_left = (const float*)d_in[3];   // [1, 8, 64]
    float* out = (float*)d_out;                    // [4096, 512]

    gemm_h_kernel<<<dim3(HD / 64, NN / 128), 128>>>(inp, W);
    scores_kernel<<<(NN * NH) / 8, 256>>>(a_left);
    attn_kernel<<<dim3(NN / 128, NH), 128>>>(Amat, out);
}

// round 8
// speedup vs baseline: 2.2387x; 2.2387x over previous
#include <cuda_runtime.h>
#include <cstdint>

#define NN   4096
#define IN_F 256
#define HD   512
#define NH   8
#define DD   64
#define TJ   32

// Scratch (no allocations allowed)
__device__ float g_h[NN * HD];      // h = inp @ W^T   [N, H*D]
__device__ float g_e1[NH * NN];     // exp(s[h][n])
__device__ float g_e2[NH * NN];     // exp(0.2*s[h][n])

__device__ __forceinline__ float to_tf32(float x) {
    float r;
    asm("cvt.rna.tf32.f32 %0, %1;" : "=f"(r) : "f"(x));
    return r;
}

__device__ __forceinline__ void mma_tf32(float* c, const uint32_t* a, const uint32_t* b) {
    asm volatile(
        "mma.sync.aligned.m16n8k8.row.col.f32.tf32.tf32.f32 "
        "{%0,%1,%2,%3}, {%4,%5,%6,%7}, {%8,%9}, {%0,%1,%2,%3};"
        : "+f"(c[0]), "+f"(c[1]), "+f"(c[2]), "+f"(c[3])
        : "r"(a[0]), "r"(a[1]), "r"(a[2]), "r"(a[3]), "r"(b[0]), "r"(b[1]));
}

// ---------------------------------------------------------------------------
// Kernel 1: h = inp @ W^T.  BM=64, BN=64, BK=16, 128 threads, 8x4 micro-tile.
// 512 CTAs -> 3.46/SM.
// ---------------------------------------------------------------------------
__global__ __launch_bounds__(128) void gemm_h_kernel(
    const float* __restrict__ inp, const float* __restrict__ W)
{
    __shared__ float smA[16][64];
    __shared__ float smB[16][64];
    const int tid = threadIdx.x;
    const int m0 = blockIdx.y * 64;
    const int n0 = blockIdx.x * 64;
    const int tx = tid & 15;
    const int ty = tid >> 4;

    float acc[8][4];
#pragma unroll
    for (int r = 0; r < 8; r++)
#pragma unroll
        for (int c = 0; c < 4; c++) acc[r][c] = 0.f;

    for (int k0 = 0; k0 < IN_F; k0 += 16) {
#pragma unroll
        for (int p = 0; p < 2; p++) {
            int idx = p * 128 + tid;
            int r = idx >> 2, q = idx & 3;
            float4 v = *(const float4*)&inp[(size_t)(m0 + r) * IN_F + k0 + 4 * q];
            smA[4 * q + 0][r] = v.x; smA[4 * q + 1][r] = v.y;
            smA[4 * q + 2][r] = v.z; smA[4 * q + 3][r] = v.w;
        }
#pragma unroll
        for (int p = 0; p < 2; p++) {
            int idx = p * 128 + tid;
            int r = idx >> 2, q = idx & 3;
            float4 v = *(const float4*)&W[(size_t)(n0 + r) * IN_F + k0 + 4 * q];
            smB[4 * q + 0][r] = v.x; smB[4 * q + 1][r] = v.y;
            smB[4 * q + 2][r] = v.z; smB[4 * q + 3][r] = v.w;
        }
        __syncthreads();
#pragma unroll
        for (int k = 0; k < 16; k++) {
            float4 a0 = *(const float4*)&smA[k][ty * 8];
            float4 a1 = *(const float4*)&smA[k][ty * 8 + 4];
            float4 b  = *(const float4*)&smB[k][tx * 4];
            float a[8] = {a0.x, a0.y, a0.z, a0.w, a1.x, a1.y, a1.z, a1.w};
            float bb[4] = {b.x, b.y, b.z, b.w};
#pragma unroll
            for (int r = 0; r < 8; r++)
#pragma unroll
                for (int c = 0; c < 4; c++) acc[r][c] += a[r] * bb[c];
        }
        __syncthreads();
    }
#pragma unroll
    for (int r = 0; r < 8; r++) {
        float4 v = make_float4(acc[r][0], acc[r][1], acc[r][2], acc[r][3]);
        *(float4*)&g_h[(size_t)(m0 + ty * 8 + r) * HD + n0 + tx * 4] = v;
    }
}

// ---------------------------------------------------------------------------
// Kernel 2: scores -> exp tables. One warp per (n,h).
// ---------------------------------------------------------------------------
__global__ __launch_bounds__(256) void scores_kernel(const float* __restrict__ a_left)
{
    int gid  = blockIdx.x * 8 + (threadIdx.x >> 5);
    int lane = threadIdx.x & 31;
    int h = gid & 7;
    int n = gid >> 3;
    float2 v = *(const float2*)&g_h[(size_t)n * HD + h * DD + lane * 2];
    float2 a = *(const float2*)&a_left[h * DD + lane * 2];
    float p = v.x * a.x + v.y * a.y;
#pragma unroll
    for (int o = 16; o > 0; o >>= 1) p += __shfl_xor_sync(0xffffffffu, p, o);
    if (lane == 0) {
        g_e1[h * NN + n] = __expf(p);
        g_e2[h * NN + n] = __expf(0.2f * p);
    }
}

// ---------------------------------------------------------------------------
// Kernel 3: attention via tf32 mma.sync (m16n8k8).
// Grid (32 row-tiles, 8 heads), 128 threads, 2 CTAs/SM.
// Per j-tile (TJ=32):
//   phase 1: Ws[128x32] = tf32( max(e1i*e1j, e2i*e2j) * optional exp(A) )
//            Vt[32x64]  = tf32( h[j, h*64.. ] )
//   denominator: per-thread row sum of Ws (consistent with mma numerator)
//   phase 2: acc[128x64] += Ws @ Vt via 64 HMMA per warp.
// ---------------------------------------------------------------------------
__global__ __launch_bounds__(128, 2) void attn_kernel(
    const float* __restrict__ Amat, float* __restrict__ out)
{
    __shared__ float Ws[128][33];   // [i][k]  A-frag + row-sum conflict-free
    __shared__ float Vt[32][72];    // [k][d]  B-frag conflict-free (8t+g)
    __shared__ float se1[128], se2[128], sden[128];

    const int tid  = threadIdx.x;
    const int lane = tid & 31;
    const int wid  = tid >> 5;
    const int h    = blockIdx.y;
    const int i0   = blockIdx.x * 128;
    const int g    = lane >> 2;     // groupID (0..7)
    const int t    = lane & 3;      // thread-in-group (0..3)

    se1[tid] = g_e1[h * NN + i0 + tid];
    se2[tid] = g_e2[h * NN + i0 + tid];
    sden[tid] = 0.f;

    float acc[2][8][4];
#pragma unroll
    for (int m = 0; m < 2; m++)
#pragma unroll
        for (int n = 0; n < 8; n++)
#pragma unroll
            for (int c = 0; c < 4; c++) acc[m][n][c] = 0.f;

    for (int j0 = 0; j0 < NN; j0 += TJ) {
        __syncthreads();   // protects Ws/Vt reuse + first-iter se1/se2

        // ---- V tile: Vt[j][d] = tf32(h[j0+j, h*64+d]) ----
        {
            const int j  = tid >> 2;
            const int qs = tid & 3;
            const float* src = &g_h[(size_t)(j0 + j) * HD + h * DD + qs * 16];
#pragma unroll
            for (int p = 0; p < 4; ++p) {
                float4 v = *(const float4*)(src + p * 4);
                float4 w = make_float4(to_tf32(v.x), to_tf32(v.y),
                                       to_tf32(v.z), to_tf32(v.w));
                *(float4*)&Vt[j][qs * 16 + p * 4] = w;
            }
        }

        // ---- weight tile Ws[128x32] ----
        {
            const float e1j = g_e1[h * NN + j0 + lane];
            const float e2j = g_e2[h * NN + j0 + lane];
            const float* arow = &Amat[(size_t)i0 * NN + j0 + lane];
#pragma unroll
            for (int p = 0; p < 32; ++p) {
                int i = p * 4 + wid;
                float a = arow[(size_t)i * NN];
                // exp(leaky_relu(si+sj)) == max(e^si e^sj, e^.2si e^.2sj); +A -> *exp(A)
                float w = fmaxf(se1[i] * e1j, se2[i] * e2j);
                if (__any_sync(0xffffffffu, a != 0.0f)) {
                    if (a != 0.0f) w *= __expf(a);
                }
                Ws[i][lane] = to_tf32(w);
            }
        }
        __syncthreads();

        // ---- denominators: row sum of Ws (one row per thread) ----
        {
            float ds = 0.f;
#pragma unroll
            for (int k = 0; k < 32; k++) ds += Ws[tid][k];
            sden[tid] += ds;
        }

        // ---- phase 2: acc += Ws @ Vt via tf32 mma ----
        const int r0 = wid * 32;
#pragma unroll
        for (int kc = 0; kc < 32; kc += 8) {
            uint32_t af[2][4];
#pragma unroll
            for (int m = 0; m < 2; m++) {
                int rb = r0 + m * 16;
                af[m][0] = __float_as_uint(Ws[rb + g][kc + t]);
                af[m][1] = __float_as_uint(Ws[rb + 8 + g][kc + t]);
                af[m][2] = __float_as_uint(Ws[rb + g][kc + t + 4]);
                af[m][3] = __float_as_uint(Ws[rb + 8 + g][kc + t + 4]);
            }
            uint32_t bf[8][2];
#pragma unroll
            for (int n = 0; n < 8; n++) {
                bf[n][0] = __float_as_uint(Vt[kc + t][n * 8 + g]);
                bf[n][1] = __float_as_uint(Vt[kc + t + 4][n * 8 + g]);
            }
#pragma unroll
            for (int m = 0; m < 2; m++)
#pragma unroll
                for (int n = 0; n < 8; n++)
                    mma_tf32(acc[m][n], af[m], bf[n]);
        }
    }
    __syncthreads();

    // ---- epilogue: normalize rows and store ----
#pragma unroll
    for (int m = 0; m < 2; m++) {
        const int ra = wid * 32 + m * 16 + g;
        const int rb = ra + 8;
        const float invA = 1.0f / sden[ra];
        const float invB = 1.0f / sden[rb];
        float* dstA = &out[(size_t)(i0 + ra) * HD + h * DD + 2 * t];
        float* dstB = &out[(size_t)(i0 + rb) * HD + h * DD + 2 * t];
#pragma unroll
        for (int n = 0; n < 8; n++) {
            *(float2*)(dstA + n * 8) = make_float2(acc[m][n][0] * invA,
                                                   acc[m][n][1] * invA);
            *(float2*)(dstB + n * 8) = make_float2(acc[m][n][2] * invB,
                                                   acc[m][n][3] * invB);
        }
    }
}

// ---------------------------------------------------------------------------
extern "C" void kernel_launch(void* const* d_in, const int* in_sizes, int n_in,
                              void* d_out, int out_size)
{
    const float* inp    = (const float*)d_in[0];   // [4096, 256]
    const float* Amat   = (const float*)d_in[1];   // [4096, 4096]
    const float* W      = (const float*)d_in[2];   // [512, 256]
    const float* a_left = (const float*)d_in[3];   // [1, 8, 64]
    float* out = (float*)d_out;                    // [4096, 512]

    gemm_h_kernel<<<dim3(HD / 64, NN / 64), 128>>>(inp, W);
    scores_kernel<<<(NN * NH) / 8, 256>>>(a_left);
    attn_kernel<<<dim3(NN / 128, NH), 128>>>(Amat, out);
}

// round 13
// speedup vs baseline: 5.8418x; 2.6095x over previous
#include <cuda_runtime.h>
#include <cstdint>

#define NN   4096
#define IN_F 256
#define HD   512
#define NH   8
#define DD   64
#define NT   (NN / 32)     // 128 j-tiles

// Scratch (no allocations allowed)
__device__ float g_h[NN * HD];            // h = inp @ W^T   [N, H*D]
__device__ float g_e1[NH * NN];           // exp(s[h][n])
__device__ float g_e2[NH * NN];           // exp(0.2*s[h][n])
__device__ unsigned char g_amask[32 * NT];// per (i-tile 128 x j-tile 32): any A != 0

__device__ __forceinline__ float to_tf32(float x) {
    float r;
    asm("cvt.rna.tf32.f32 %0, %1;" : "=f"(r) : "f"(x));
    return r;
}

__device__ __forceinline__ void mma_tf32(float* c, const uint32_t* a, const uint32_t* b) {
    asm volatile(
        "mma.sync.aligned.m16n8k8.row.col.f32.tf32.tf32.f32 "
        "{%0,%1,%2,%3}, {%4,%5,%6,%7}, {%8,%9}, {%0,%1,%2,%3};"
        : "+f"(c[0]), "+f"(c[1]), "+f"(c[2]), "+f"(c[3])
        : "r"(a[0]), "r"(a[1]), "r"(a[2]), "r"(a[3]), "r"(b[0]), "r"(b[1]));
}

// ---------------------------------------------------------------------------
// Kernel 1: h = inp @ W^T.  BM=64, BN=32, BK=16, 128 threads, 4x4 micro-tile.
// 1024 CTAs -> ~6.9/SM (fixes grid-limited occupancy seen at 512 CTAs).
// ---------------------------------------------------------------------------
__global__ __launch_bounds__(128) void gemm_h_kernel(
    const float* __restrict__ inp, const float* __restrict__ W)
{
    __shared__ float smA[16][64];
    __shared__ float smB[16][32];
    const int tid = threadIdx.x;
    const int m0 = blockIdx.y * 64;
    const int n0 = blockIdx.x * 32;
    const int tx = tid & 7;       // 8 col-groups of 4
    const int ty = tid >> 3;      // 16 row-groups of 4

    float acc[4][4];
#pragma unroll
    for (int r = 0; r < 4; r++)
#pragma unroll
        for (int c = 0; c < 4; c++) acc[r][c] = 0.f;

    for (int k0 = 0; k0 < IN_F; k0 += 16) {
#pragma unroll
        for (int p = 0; p < 2; p++) {
            int idx = p * 128 + tid;
            int r = idx >> 2, q = idx & 3;
            float4 v = *(const float4*)&inp[(size_t)(m0 + r) * IN_F + k0 + 4 * q];
            smA[4 * q + 0][r] = v.x; smA[4 * q + 1][r] = v.y;
            smA[4 * q + 2][r] = v.z; smA[4 * q + 3][r] = v.w;
        }
        {
            int r = tid >> 2, q = tid & 3;
            float4 v = *(const float4*)&W[(size_t)(n0 + r) * IN_F + k0 + 4 * q];
            smB[4 * q + 0][r] = v.x; smB[4 * q + 1][r] = v.y;
            smB[4 * q + 2][r] = v.z; smB[4 * q + 3][r] = v.w;
        }
        __syncthreads();
#pragma unroll
        for (int k = 0; k < 16; k++) {
            float4 a4 = *(const float4*)&smA[k][ty * 4];
            float4 b4 = *(const float4*)&smB[k][tx * 4];
            float a[4] = {a4.x, a4.y, a4.z, a4.w};
            float b[4] = {b4.x, b4.y, b4.z, b4.w};
#pragma unroll
            for (int r = 0; r < 4; r++)
#pragma unroll
                for (int c = 0; c < 4; c++) acc[r][c] += a[r] * b[c];
        }
        __syncthreads();
    }
#pragma unroll
    for (int r = 0; r < 4; r++) {
        float4 v = make_float4(acc[r][0], acc[r][1], acc[r][2], acc[r][3]);
        *(float4*)&g_h[(size_t)(m0 + ty * 4 + r) * HD + n0 + tx * 4] = v;
    }
}

// ---------------------------------------------------------------------------
// Kernel 2: scores -> exp tables. One warp per (n,h).
// ---------------------------------------------------------------------------
__global__ __launch_bounds__(256) void scores_kernel(const float* __restrict__ a_left)
{
    int gid  = blockIdx.x * 8 + (threadIdx.x >> 5);
    int lane = threadIdx.x & 31;
    int h = gid & 7;
    int n = gid >> 3;
    float2 v = *(const float2*)&g_h[(size_t)n * HD + h * DD + lane * 2];
    float2 a = *(const float2*)&a_left[h * DD + lane * 2];
    float p = v.x * a.x + v.y * a.y;
#pragma unroll
    for (int o = 16; o > 0; o >>= 1) p += __shfl_xor_sync(0xffffffffu, p, o);
    if (lane == 0) {
        g_e1[h * NN + n] = __expf(p);
        g_e2[h * NN + n] = __expf(0.2f * p);
    }
}

// ---------------------------------------------------------------------------
// Kernel 2b: A nonzero mask per (i-tile 128 x j-tile 32).
// Grid (NT, 32), 256 threads. 64MB scan, DRAM-bound (~12us).
// ---------------------------------------------------------------------------
__global__ __launch_bounds__(256) void amask_kernel(const float* __restrict__ A)
{
    const int it = blockIdx.y, jt = blockIdx.x;
    const int tid = threadIdx.x;
    const float* base = A + (size_t)it * 128 * NN + jt * 32;
    int any = 0;
#pragma unroll
    for (int rr = 0; rr < 4; rr++) {
        int row = rr * 32 + (tid >> 3);
        float4 v = *(const float4*)(base + (size_t)row * NN + (tid & 7) * 4);
        any |= (v.x != 0.f) | (v.y != 0.f) | (v.z != 0.f) | (v.w != 0.f);
    }
    int r = __syncthreads_or(any);
    if (tid == 0) g_amask[it * NT + jt] = (unsigned char)(r ? 1 : 0);
}

// ---------------------------------------------------------------------------
// Kernel 3: attention via tf32 mma.sync, register-resident weight fragments.
// Grid (32, 8) = 256 CTAs, 256 threads (8 warps, each owns m16 x n64),
// 2 CTAs/SM -> 4 warps/SMSP. Per j-tile (32):
//   - A-fragments computed in registers: w = max(e1i*e1j, e2i*e2j)
//     (e1i/e2i hoisted; 16 L1-hit LDGs for e1j/e2j per tile)
//   - rare path (g_amask set): multiply exp(A) per fragment element
//   - V tile double-buffered in smem (one barrier per tile)
//   - denominators: per-lane partial sums, one quad-reduce at the end
// ---------------------------------------------------------------------------
__global__ __launch_bounds__(256, 2) void attn_kernel(
    const float* __restrict__ Amat, float* __restrict__ out)
{
    __shared__ float Vt[2][32][72];       // [buf][k][d], 72 -> conflict-free B-frag LDS
    __shared__ unsigned char smask[NT];

    const int tid  = threadIdx.x;
    const int lane = tid & 31;
    const int wid  = tid >> 5;            // 0..7
    const int g    = lane >> 2;           // groupID 0..7
    const int t    = lane & 3;            // thread-in-group 0..3
    const int h    = blockIdx.y;
    const int i0   = blockIdx.x * 128;

    if (tid < NT) smask[tid] = g_amask[blockIdx.x * NT + tid];

    // per-warp constant row exponentials (rows ra, rb = ra+8)
    const int ra = wid * 16 + g;
    const int rb = ra + 8;
    const float e1A = g_e1[h * NN + i0 + ra], e2A = g_e2[h * NN + i0 + ra];
    const float e1B = g_e1[h * NN + i0 + rb], e2B = g_e2[h * NN + i0 + rb];

    float dA = 0.f, dB = 0.f;
    float acc[8][4];
#pragma unroll
    for (int n = 0; n < 8; n++)
#pragma unroll
        for (int c = 0; c < 4; c++) acc[n][c] = 0.f;

    // V fill: thread handles row j = tid>>3, 8 cols at (tid&7)*8
    const int vj = tid >> 3, vc = (tid & 7) * 8;

    // pre-fill tile 0
    {
        const float* src = &g_h[(size_t)vj * HD + h * DD + vc];
        float4 v0 = *(const float4*)(src);
        float4 v1 = *(const float4*)(src + 4);
        *(float4*)&Vt[0][vj][vc]     = make_float4(to_tf32(v0.x), to_tf32(v0.y),
                                                   to_tf32(v0.z), to_tf32(v0.w));
        *(float4*)&Vt[0][vj][vc + 4] = make_float4(to_tf32(v1.x), to_tf32(v1.y),
                                                   to_tf32(v1.z), to_tf32(v1.w));
    }
    __syncthreads();

    for (int it = 0; it < NT; ++it) {
        const int s  = it & 1;
        const int j0 = it * 32;

        // prefetch next V tile into the other buffer
        if (it + 1 < NT) {
            const float* src = &g_h[(size_t)(j0 + 32 + vj) * HD + h * DD + vc];
            float4 v0 = *(const float4*)(src);
            float4 v1 = *(const float4*)(src + 4);
            *(float4*)&Vt[s ^ 1][vj][vc]     = make_float4(to_tf32(v0.x), to_tf32(v0.y),
                                                           to_tf32(v0.z), to_tf32(v0.w));
            *(float4*)&Vt[s ^ 1][vj][vc + 4] = make_float4(to_tf32(v1.x), to_tf32(v1.y),
                                                           to_tf32(v1.z), to_tf32(v1.w));
        }

        // j exponentials for this thread's 8 columns (L1-resident)
        const float* pe1 = &g_e1[h * NN + j0];
        const float* pe2 = &g_e2[h * NN + j0];
        float e1j[8], e2j[8];
#pragma unroll
        for (int q = 0; q < 4; q++) {
            e1j[2 * q]     = __ldg(pe1 + q * 8 + t);
            e1j[2 * q + 1] = __ldg(pe1 + q * 8 + t + 4);
            e2j[2 * q]     = __ldg(pe2 + q * 8 + t);
            e2j[2 * q + 1] = __ldg(pe2 + q * 8 + t + 4);
        }

        const bool hasA = smask[it] != 0;   // warp-uniform

        // A-fragments in registers + denominator partials + MMA
        uint32_t af[4][4];
#pragma unroll
        for (int q = 0; q < 4; q++) {
            float w0 = fmaxf(e1A * e1j[2 * q],     e2A * e2j[2 * q]);      // (ra, q*8+t)
            float w1 = fmaxf(e1B * e1j[2 * q],     e2B * e2j[2 * q]);      // (rb, q*8+t)
            float w2 = fmaxf(e1A * e1j[2 * q + 1], e2A * e2j[2 * q + 1]);  // (ra, q*8+t+4)
            float w3 = fmaxf(e1B * e1j[2 * q + 1], e2B * e2j[2 * q + 1]);  // (rb, q*8+t+4)
            if (hasA) {  // rare, correct path: logits + A  ->  weights * exp(A)
                float a;
                a = Amat[(size_t)(i0 + ra) * NN + j0 + q * 8 + t];
                if (a != 0.f) w0 *= __expf(a);
                a = Amat[(size_t)(i0 + rb) * NN + j0 + q * 8 + t];
                if (a != 0.f) w1 *= __expf(a);
                a = Amat[(size_t)(i0 + ra) * NN + j0 + q * 8 + t + 4];
                if (a != 0.f) w2 *= __expf(a);
                a = Amat[(size_t)(i0 + rb) * NN + j0 + q * 8 + t + 4];
                if (a != 0.f) w3 *= __expf(a);
            }
            w0 = to_tf32(w0); w1 = to_tf32(w1); w2 = to_tf32(w2); w3 = to_tf32(w3);
            dA += w0 + w2;
            dB += w1 + w3;
            af[q][0] = __float_as_uint(w0);
            af[q][1] = __float_as_uint(w1);
            af[q][2] = __float_as_uint(w2);
            af[q][3] = __float_as_uint(w3);
        }

#pragma unroll
        for (int q = 0; q < 4; q++) {
            uint32_t bf[8][2];
#pragma unroll
            for (int n = 0; n < 8; n++) {
                bf[n][0] = __float_as_uint(Vt[s][q * 8 + t][n * 8 + g]);
                bf[n][1] = __float_as_uint(Vt[s][q * 8 + t + 4][n * 8 + g]);
            }
#pragma unroll
            for (int n = 0; n < 8; n++)
                mma_tf32(acc[n], af[q], bf[n]);
        }

        __syncthreads();   // Vt[s] reads done; Vt[s^1] writes done
    }

    // denominator: reduce partials across the quad (t = 0..3)
    dA += __shfl_xor_sync(0xffffffffu, dA, 1);
    dA += __shfl_xor_sync(0xffffffffu, dA, 2);
    dB += __shfl_xor_sync(0xffffffffu, dB, 1);
    dB += __shfl_xor_sync(0xffffffffu, dB, 2);
    const float invA = 1.0f / dA;
    const float invB = 1.0f / dB;

    float* dstA = &out[(size_t)(i0 + ra) * HD + h * DD + 2 * t];
    float* dstB = &out[(size_t)(i0 + rb) * HD + h * DD + 2 * t];
#pragma unroll
    for (int n = 0; n < 8; n++) {
        *(float2*)(dstA + n * 8) = make_float2(acc[n][0] * invA, acc[n][1] * invA);
        *(float2*)(dstB + n * 8) = make_float2(acc[n][2] * invB, acc[n][3] * invB);
    }
}

// ---------------------------------------------------------------------------
extern "C" void kernel_launch(void* const* d_in, const int* in_sizes, int n_in,
                              void* d_out, int out_size)
{
    const float* inp    = (const float*)d_in[0];   // [4096, 256]
    const float* Amat   = (const float*)d_in[1];   // [4096, 4096]
    const float* W      = (const float*)d_in[2];   // [512, 256]
    const float* a_left = (const float*)d_in[3];   // [1, 8, 64]
    float* out = (float*)d_out;                    // [4096, 512]

    gemm_h_kernel<<<dim3(HD / 32, NN / 64), 128>>>(inp, W);
    amask_kernel<<<dim3(NT, 32), 256>>>(Amat);
    scores_kernel<<<(NN * NH) / 8, 256>>>(a_left);
    attn_kernel<<<dim3(NN / 128, NH), 256>>>(Amat, out);
}